// round 5
// baseline (speedup 1.0000x reference)
#include <cuda_runtime.h>
#include <math.h>

#define Ld 2048
#define Sd 2048
#define NBd 4
#define Ed 512
#define Hd 8
#define Dd 64
#define Md (Ld * NBd)        // 8192 rows in (L,N) flattening
#define BATCHd (NBd * Hd)    // 32

// Scratch (static device globals — allocation-free per harness rules)
__device__ float g_q[(size_t)BATCHd * Ld * Dd];     // [n][h][l][d], q already +rel_u and *1/8
__device__ float g_k[(size_t)BATCHd * Sd * Dd];     // [n][h][s][d]
__device__ float g_v[(size_t)BATCHd * Sd * Dd];     // [n][h][s][d]
__device__ float g_sc[(size_t)BATCHd * Ld * Sd];    // scores / probs, 512 MB
__device__ float g_ao[(size_t)Md * Ed];             // attention output (L,N,E)

// ---------------------------------------------------------------------------
// Projection GEMM: Y = X @ W^T + bias  (optionally + rel, * scale)
// mode 0/1/2: scatter into g_q/g_k/g_v as [n][h][l][d]
// mode 3:     X is g_ao (param ignored), plain write Y[m][e] to outp
// ---------------------------------------------------------------------------
__global__ __launch_bounds__(256) void proj_kernel(
    const float* __restrict__ X, const float* __restrict__ W,
    const float* __restrict__ bias, const float* __restrict__ rel,
    float scale, int mode, float* __restrict__ outp)
{
    __shared__ float As[32][68];
    __shared__ float Bs[32][68];
    const float* Xp = (mode == 3) ? (const float*)g_ao : X;

    int tid = threadIdx.x;
    int e0 = blockIdx.x * 64;
    int m0 = blockIdx.y * 64;
    int tx = tid & 15, ty = tid >> 4;
    float acc[4][4] = {};

    for (int kt = 0; kt < Ed; kt += 32) {
        for (int i = tid; i < 512; i += 256) {
            int row = i >> 3, c4 = (i & 7) << 2;
            float4 a = *(const float4*)(Xp + (size_t)(m0 + row) * Ed + kt + c4);
            As[c4 + 0][row] = a.x; As[c4 + 1][row] = a.y;
            As[c4 + 2][row] = a.z; As[c4 + 3][row] = a.w;
            float4 b = *(const float4*)(W + (size_t)(e0 + row) * Ed + kt + c4);
            Bs[c4 + 0][row] = b.x; Bs[c4 + 1][row] = b.y;
            Bs[c4 + 2][row] = b.z; Bs[c4 + 3][row] = b.w;
        }
        __syncthreads();
        #pragma unroll
        for (int kk = 0; kk < 32; kk++) {
            float4 a = *(const float4*)&As[kk][ty << 2];
            float4 b = *(const float4*)&Bs[kk][tx << 2];
            float av[4] = {a.x, a.y, a.z, a.w};
            float bv[4] = {b.x, b.y, b.z, b.w};
            #pragma unroll
            for (int i = 0; i < 4; i++)
                #pragma unroll
                for (int j = 0; j < 4; j++)
                    acc[i][j] += av[i] * bv[j];
        }
        __syncthreads();
    }

    float* dst = (mode == 0) ? g_q : (mode == 1) ? g_k : (mode == 2) ? g_v : outp;
    #pragma unroll
    for (int i = 0; i < 4; i++) {
        int m = m0 + (ty << 2) + i;
        #pragma unroll
        for (int j = 0; j < 4; j++) {
            int e = e0 + (tx << 2) + j;
            float v = acc[i][j] + bias[e];
            if (rel) v += rel[e];
            v *= scale;
            if (mode < 3) {
                int l = m / NBd, n = m % NBd;   // X rows are (l, n)
                int h = e / Dd, d = e % Dd;
                dst[((size_t)(n * Hd + h) * Ld + l) * Dd + d] = v;
            } else {
                dst[(size_t)m * Ed + e] = v;
            }
        }
    }
}

// ---------------------------------------------------------------------------
// Batched QK^T: scores[b][l][s] = sum_d q[b][l][d] * k[b][s][d]
// (q already carries the 1/sqrt(D) scale and +rel_u)
// ---------------------------------------------------------------------------
__global__ __launch_bounds__(256) void qk_kernel()
{
    __shared__ float Qs[64][68];
    __shared__ float Ks[64][68];
    int tid = threadIdx.x;
    int s0 = blockIdx.x * 64;
    int l0 = blockIdx.y * 64;
    int b  = blockIdx.z;
    const float* Q = g_q + (size_t)b * Ld * Dd;
    const float* K = g_k + (size_t)b * Sd * Dd;

    for (int i = tid; i < 1024; i += 256) {
        int row = i >> 4, c4 = (i & 15) << 2;
        float4 q = *(const float4*)(Q + (size_t)(l0 + row) * Dd + c4);
        Qs[c4 + 0][row] = q.x; Qs[c4 + 1][row] = q.y;
        Qs[c4 + 2][row] = q.z; Qs[c4 + 3][row] = q.w;
        float4 k = *(const float4*)(K + (size_t)(s0 + row) * Dd + c4);
        Ks[c4 + 0][row] = k.x; Ks[c4 + 1][row] = k.y;
        Ks[c4 + 2][row] = k.z; Ks[c4 + 3][row] = k.w;
    }
    __syncthreads();

    int tx = tid & 15, ty = tid >> 4;
    float acc[4][4] = {};
    #pragma unroll
    for (int kk = 0; kk < 64; kk++) {
        float4 a = *(const float4*)&Qs[kk][ty << 2];
        float4 b4 = *(const float4*)&Ks[kk][tx << 2];
        float av[4] = {a.x, a.y, a.z, a.w};
        float bv[4] = {b4.x, b4.y, b4.z, b4.w};
        #pragma unroll
        for (int i = 0; i < 4; i++)
            #pragma unroll
            for (int j = 0; j < 4; j++)
                acc[i][j] += av[i] * bv[j];
    }

    float* out = g_sc + (size_t)b * Ld * Sd;
    #pragma unroll
    for (int i = 0; i < 4; i++) {
        int l = l0 + (ty << 2) + i;
        float4 o = make_float4(acc[i][0], acc[i][1], acc[i][2], acc[i][3]);
        *(float4*)(out + (size_t)l * Sd + s0 + (tx << 2)) = o;
    }
}

// ---------------------------------------------------------------------------
// Softmax in place over s (per l,n,h) + head-mean written to att_weights.
// One CTA per (l, n), loops over 8 heads. 256 threads, 8 elems/thread.
// ---------------------------------------------------------------------------
__global__ __launch_bounds__(256) void softmax_kernel(float* __restrict__ attw)
{
    int l = blockIdx.x, n = blockIdx.y;
    int tid = threadIdx.x;
    __shared__ float red[8];
    float mean[8] = {0, 0, 0, 0, 0, 0, 0, 0};

    for (int h = 0; h < Hd; h++) {
        float* row = g_sc + ((size_t)(n * Hd + h) * Ld + l) * Sd;
        float x[8];
        float mx = -1e30f;
        #pragma unroll
        for (int i = 0; i < 8; i++) {
            x[i] = row[tid + (i << 8)];
            mx = fmaxf(mx, x[i]);
        }
        #pragma unroll
        for (int o = 16; o; o >>= 1) mx = fmaxf(mx, __shfl_xor_sync(0xffffffffu, mx, o));
        if ((tid & 31) == 0) red[tid >> 5] = mx;
        __syncthreads();
        if (tid < 32) {
            float w = (tid < 8) ? red[tid] : -1e30f;
            #pragma unroll
            for (int o = 4; o; o >>= 1) w = fmaxf(w, __shfl_xor_sync(0xffffffffu, w, o));
            if (tid == 0) red[0] = w;
        }
        __syncthreads();
        mx = red[0];
        __syncthreads();

        float sum = 0.f;
        #pragma unroll
        for (int i = 0; i < 8; i++) {
            x[i] = __expf(x[i] - mx);
            sum += x[i];
        }
        #pragma unroll
        for (int o = 16; o; o >>= 1) sum += __shfl_xor_sync(0xffffffffu, sum, o);
        if ((tid & 31) == 0) red[tid >> 5] = sum;
        __syncthreads();
        if (tid < 32) {
            float w = (tid < 8) ? red[tid] : 0.f;
            #pragma unroll
            for (int o = 4; o; o >>= 1) w += __shfl_xor_sync(0xffffffffu, w, o);
            if (tid == 0) red[0] = w;
        }
        __syncthreads();
        float inv = 1.0f / red[0];
        __syncthreads();

        #pragma unroll
        for (int i = 0; i < 8; i++) {
            float p = x[i] * inv;
            row[tid + (i << 8)] = p;
            mean[i] += p;
        }
    }

    float* aw = attw + ((size_t)n * Ld + l) * Sd;
    #pragma unroll
    for (int i = 0; i < 8; i++)
        aw[tid + (i << 8)] = mean[i] * 0.125f;
}

// ---------------------------------------------------------------------------
// Batched PV: out[b][l][d] = sum_s P[b][l][s] * V[b][s][d], written to (L,N,E)
// ---------------------------------------------------------------------------
__global__ __launch_bounds__(256) void pv_kernel()
{
    __shared__ float Ps[32][68];
    __shared__ float Vs[32][64];
    int tid = threadIdx.x;
    int l0 = blockIdx.x * 64;
    int b  = blockIdx.y;
    int n = b / Hd, h = b % Hd;
    const float* P = g_sc + (size_t)b * Ld * Sd;
    const float* V = g_v + (size_t)b * Sd * Dd;
    int tx = tid & 15, ty = tid >> 4;
    float acc[4][4] = {};

    for (int st = 0; st < Sd; st += 32) {
        for (int i = tid; i < 512; i += 256) {
            int row = i >> 3, c4 = (i & 7) << 2;
            float4 p = *(const float4*)(P + (size_t)(l0 + row) * Sd + st + c4);
            Ps[c4 + 0][row] = p.x; Ps[c4 + 1][row] = p.y;
            Ps[c4 + 2][row] = p.z; Ps[c4 + 3][row] = p.w;
            int vrow = i >> 4, vc4 = (i & 15) << 2;
            float4 v = *(const float4*)(V + (size_t)(st + vrow) * Dd + vc4);
            *(float4*)&Vs[vrow][vc4] = v;
        }
        __syncthreads();
        #pragma unroll
        for (int kk = 0; kk < 32; kk++) {
            float4 a  = *(const float4*)&Ps[kk][ty << 2];
            float4 b4 = *(const float4*)&Vs[kk][tx << 2];
            float av[4] = {a.x, a.y, a.z, a.w};
            float bv[4] = {b4.x, b4.y, b4.z, b4.w};
            #pragma unroll
            for (int i = 0; i < 4; i++)
                #pragma unroll
                for (int j = 0; j < 4; j++)
                    acc[i][j] += av[i] * bv[j];
        }
        __syncthreads();
    }

    #pragma unroll
    for (int i = 0; i < 4; i++) {
        int l = l0 + (ty << 2) + i;
        float4 o = make_float4(acc[i][0], acc[i][1], acc[i][2], acc[i][3]);
        *(float4*)(g_ao + ((size_t)l * NBd + n) * Ed + h * Dd + (tx << 2)) = o;
    }
}

// ---------------------------------------------------------------------------
extern "C" void kernel_launch(void* const* d_in, const int* in_sizes, int n_in,
                              void* d_out, int out_size)
{
    const float* query = (const float*)d_in[0];
    const float* key   = (const float*)d_in[1];
    const float* value = (const float*)d_in[2];
    // d_in[3] sin_pos_enc: unused — rel_shift term is constant over the
    // softmax axis in the reference and cancels exactly.
    const float* W     = (const float*)d_in[4];   // (3E, E)
    const float* bias  = (const float*)d_in[5];   // (3E,)
    const float* out_w = (const float*)d_in[6];
    const float* out_b = (const float*)d_in[7];
    // d_in[8] rel_proj_w: unused (cancels)
    const float* rel_u = (const float*)d_in[9];   // (H,D) == E contiguous floats
    // d_in[10] rel_v: unused (cancels)

    float* out  = (float*)d_out;                       // (L, N, E)
    float* attw = out + (size_t)Ld * NBd * Ed;         // (N, L, S)

    dim3 gp(Ed / 64, Md / 64);
    // q_eff = (q + rel_u) / sqrt(D)
    proj_kernel<<<gp, 256>>>(query, W,                 bias,          rel_u,   0.125f, 0, nullptr);
    proj_kernel<<<gp, 256>>>(key,   W + Ed * Ed,       bias + Ed,     nullptr, 1.0f,   1, nullptr);
    proj_kernel<<<gp, 256>>>(value, W + 2 * Ed * Ed,   bias + 2 * Ed, nullptr, 1.0f,   2, nullptr);

    qk_kernel<<<dim3(Sd / 64, Ld / 64, BATCHd), 256>>>();
    softmax_kernel<<<dim3(Ld, NBd), 256>>>(attw);
    pv_kernel<<<dim3(Ld / 64, BATCHd), 256>>>();

    proj_kernel<<<gp, 256>>>(nullptr, out_w, out_b, nullptr, 1.0f, 3, out);
}